// round 7
// baseline (speedup 1.0000x reference)
#include <cuda_runtime.h>
#include <mma.h>
#include <cstdint>
#include <cstddef>

using namespace nvcuda;

#define Bv   2
#define Sv   2048
#define Hv   2048
#define NHv  16
#define HDv  128
#define BSv  256
#define Mtot (Bv * Sv)
#define ATT_SCALE 0.08838834764831843f  // 1/sqrt(128)

// ---------------- scratch (__device__ globals, allocation-free rule) -------
__device__ float g_q[(size_t)Mtot * Hv];
__device__ float g_k[(size_t)Mtot * Hv];
__device__ float g_v[(size_t)Mtot * Hv];
__device__ float g_o[(size_t)Mtot * Hv];
__device__ float g_xr[(size_t)Mtot * Hv];
__device__ float g_wq[(size_t)Hv * Hv];
__device__ float g_wk[(size_t)Hv * Hv];
__device__ float g_wv[(size_t)Hv * Hv];
__device__ float g_wo[(size_t)Hv * Hv];

// ---------------- helpers ---------------------------------------------------
__device__ __forceinline__ float to_tf32(float x) {
    float y;
    asm("cvt.rna.tf32.f32 %0, %1;" : "=f"(y) : "f"(x));
    return y;
}

__device__ __forceinline__ uint32_t smem_u32(const void* p) {
    uint32_t a;
    asm("{ .reg .u64 t; cvta.to.shared.u64 t, %1; cvt.u32.u64 %0, t; }" : "=r"(a) : "l"(p));
    return a;
}

__device__ __forceinline__ void cp_async16(uint32_t saddr, const void* gptr) {
    asm volatile("cp.async.cg.shared.global [%0], [%1], 16;" :: "r"(saddr), "l"(gptr));
}
#define CP_COMMIT() asm volatile("cp.async.commit_group;")
#define CP_WAIT(n)  asm volatile("cp.async.wait_group %0;" :: "n"(n))

// ---------------- merged rounding pre-pass (one launch) ---------------------
#define NX4 (Mtot * Hv / 4)   // 2,097,152
#define NW4 (Hv * Hv / 4)     // 1,048,576

__global__ void __launch_bounds__(256) round_all_k(
    const float4* __restrict__ X,  const float4* __restrict__ Wq,
    const float4* __restrict__ Wk, const float4* __restrict__ Wv,
    const float4* __restrict__ Wo)
{
    int i = blockIdx.x * 256 + threadIdx.x;
    const float4* s; float4* d; int off;
    if (i < NX4)               { s = X;  d = (float4*)g_xr; off = i; }
    else if (i < NX4 + NW4)    { s = Wq; d = (float4*)g_wq; off = i - NX4; }
    else if (i < NX4 + 2*NW4)  { s = Wk; d = (float4*)g_wk; off = i - NX4 - NW4; }
    else if (i < NX4 + 3*NW4)  { s = Wv; d = (float4*)g_wv; off = i - NX4 - 2*NW4; }
    else                       { s = Wo; d = (float4*)g_wo; off = i - NX4 - 3*NW4; }
    float4 v = s[off];
    v.x = to_tf32(v.x); v.y = to_tf32(v.y);
    v.z = to_tf32(v.z); v.w = to_tf32(v.w);
    d[off] = v;
}

// ===========================================================================
// Pipelined tf32 wmma GEMM: C[M,N] = A[M,K] @ Bw[N,K]^T (K-major, pre-rounded)
// CTA tile 256x128x64, 8 warps (4x2) with 64x64 warp tiles, 2-stage cp.async,
// 1 CTA/SM (R4-proven config, BK doubled to halve sync boundaries).
// do_round=1 -> epilogue RNA-rounds C to tf32 (for Q/K/V feeding attention).
// ===========================================================================
#define BM 256
#define BN 128
#define BK 64
#define STR 68                       // 64 + 4 pad floats (16B-aligned rows)
#define A_FLTS (BM * STR)            // 17408
#define B_FLTS (BN * STR)            // 8704
#define STAGE_FLTS (A_FLTS + B_FLTS) // 26112
#define GEMM_SMEM (2 * STAGE_FLTS * 4)   // 208896 B -> 1 CTA/SM

__device__ __forceinline__ void stage_load(
    float* stg, const float* __restrict__ Ag, const float* __restrict__ Bg,
    int K, int tid)
{
#pragma unroll
    for (int i = 0; i < 16; i++) {     // A: 256 rows x 16 x 16B
        int id = tid + i * 256;
        int r = id >> 4, c = id & 15;
        cp_async16(smem_u32(stg + r * STR + c * 4), Ag + (size_t)r * K + c * 4);
    }
#pragma unroll
    for (int i = 0; i < 8; i++) {      // B: 128 rows x 16 x 16B
        int id = tid + i * 256;
        int r = id >> 4, c = id & 15;
        cp_async16(smem_u32(stg + A_FLTS + r * STR + c * 4), Bg + (size_t)r * K + c * 4);
    }
}

__global__ void __launch_bounds__(256, 1) gemm_pipe(
    const float* __restrict__ A, const float* __restrict__ Bw,
    float* __restrict__ C, int M, int N, int K, int do_round)
{
    extern __shared__ __align__(16) float sm[];

    const int tid = threadIdx.x;
    const int wid = tid >> 5;
    const int m0 = blockIdx.y * BM;
    const int n0 = blockIdx.x * BN;
    const int wm = wid & 3;    // 4 warp rows x 64 m
    const int wn = wid >> 2;   // 2 warp cols x 64 n

    const float* Abase = A + (size_t)m0 * K;
    const float* Bbase = Bw + (size_t)n0 * K;
    const int KT = K / BK;     // 32

    wmma::fragment<wmma::accumulator, 16, 16, 8, float> acc[4][4];
#pragma unroll
    for (int i = 0; i < 4; i++)
#pragma unroll
        for (int j = 0; j < 4; j++) wmma::fill_fragment(acc[i][j], 0.0f);

    // prologue: stage 0 <- k-tile 0
    stage_load(sm, Abase, Bbase, K, tid);
    CP_COMMIT();

    for (int kt = 0; kt < KT; kt++) {
        CP_WAIT(0);                 // k-tile kt resident
        __syncthreads();            // all warps past compute kt-1 -> other stage free

        int tn = kt + 1;
        if (tn < KT)
            stage_load(sm + (tn & 1) * STAGE_FLTS, Abase + (size_t)tn * BK,
                       Bbase + (size_t)tn * BK, K, tid);
        CP_COMMIT();

        const float* sA = sm + (kt & 1) * STAGE_FLTS;
        const float* sB = sA + A_FLTS;

#pragma unroll
        for (int kk = 0; kk < 8; kk++) {
            wmma::fragment<wmma::matrix_a, 16, 16, 8, wmma::precision::tf32, wmma::row_major> af[4];
            wmma::fragment<wmma::matrix_b, 16, 16, 8, wmma::precision::tf32, wmma::col_major> bf[4];
#pragma unroll
            for (int i = 0; i < 4; i++)
                wmma::load_matrix_sync(af[i], sA + (wm * 64 + i * 16) * STR + kk * 8, STR);
#pragma unroll
            for (int j = 0; j < 4; j++)
                wmma::load_matrix_sync(bf[j], sB + (wn * 64 + j * 16) * STR + kk * 8, STR);
#pragma unroll
            for (int j = 0; j < 4; j++)
#pragma unroll
                for (int i = 0; i < 4; i++)
                    wmma::mma_sync(acc[i][j], af[i], bf[j], acc[i][j]);
        }
    }

#pragma unroll
    for (int i = 0; i < 4; i++)
#pragma unroll
        for (int j = 0; j < 4; j++) {
            if (do_round) {
#pragma unroll
                for (int t = 0; t < acc[i][j].num_elements; t++)
                    acc[i][j].x[t] = to_tf32(acc[i][j].x[t]);
            }
            wmma::store_matrix_sync(
                C + (size_t)(m0 + wm * 64 + i * 16) * N + n0 + wn * 64 + j * 16,
                acc[i][j], N, wmma::mem_row_major);
        }
}

// ===========================================================================
// Attention with per-block softmax. Diagonal block: only subtiles s<=p are
// unmasked (p = (qbase>>6)&3); skipped subtiles have exactly zero weight.
// K/V subtiles double-buffered via cp.async, one subtile ahead.
// ===========================================================================
#define QT  64
#define AST 132   // 128 + 4 pad
#define SST 260   // 256 + 4 pad

__global__ void __launch_bounds__(256) attn_kernel()
{
    extern __shared__ __align__(16) float sm[];
    float* shQ  = sm;                          // [64][AST]
    float* shKV[2] = { shQ + QT * AST, shQ + 2 * QT * AST };
    float* shS  = shQ + 3 * QT * AST;          // [64][SST]

    const int tid = threadIdx.x;
    const int wid = tid >> 5;
    const int qt = blockIdx.x;
    const int h  = blockIdx.y;
    const int b  = blockIdx.z;
    const int qbase = qt * QT;
    const int bi = qbase >> 8;
    const int pdiag = (qbase >> 6) & 3;        // last needed subtile on diagonal

    const float* Qp    = g_q + ((size_t)b * Sv + qbase) * Hv + h * HDv;
    const float* Kbase = g_k + ((size_t)b * Sv) * Hv + h * HDv;
    const float* Vbase = g_v + ((size_t)b * Sv) * Hv + h * HDv;

    auto load64 = [&](float* dst, const float* src) {
#pragma unroll
        for (int i = 0; i < 8; i++) {
            int id = tid + i * 256;
            int r = id >> 5, c4 = id & 31;
            cp_async16(smem_u32(dst + r * AST + c4 * 4), src + (size_t)r * Hv + c4 * 4);
        }
    };

    load64(shQ, Qp);
    load64(shKV[0], Kbase);   // K(jb=0, sub=0)
    CP_COMMIT();

    wmma::fragment<wmma::accumulator, 16, 16, 8, float> acc_o[2][2];
#pragma unroll
    for (int i = 0; i < 2; i++)
#pragma unroll
        for (int j = 0; j < 2; j++) wmma::fill_fragment(acc_o[i][j], 0.0f);

    const int wms = wid & 3,  wns = wid >> 2;   // S phase: 16 rows x 32 cols
    const int wmo = wid & 1,  wno = wid >> 1;   // O phase: 32 rows x 32 cols

    const int row  = tid >> 2;
    const int part = tid & 3;
    const int qoff = (qbase & 255) + row;

    for (int jb = 0; jb <= bi; jb++) {
        const float* Kj = Kbase + (size_t)jb * BSv * Hv;
        const float* Vj = Vbase + (size_t)jb * BSv * Hv;
        const int send = (jb == bi) ? pdiag : 3;   // last subtile needed

        // ---- S phase: subtiles 0..send of 64 keys ----
        for (int s = 0; s <= send; s++) {
            CP_WAIT(0);
            __syncthreads();
            if (s < send)  load64(shKV[(s + 1) & 1], Kj + (size_t)(s + 1) * 64 * Hv);
            else           load64(shKV[(send + 1) & 1], Vj);          // V(jb,0)
            CP_COMMIT();

            const float* kb = shKV[s & 1];
            wmma::fragment<wmma::accumulator, 16, 16, 8, float> accs[2];
            wmma::fill_fragment(accs[0], 0.0f);
            wmma::fill_fragment(accs[1], 0.0f);
#pragma unroll
            for (int k = 0; k < HDv; k += 8) {
                wmma::fragment<wmma::matrix_a, 16, 16, 8, wmma::precision::tf32, wmma::row_major> af;
                wmma::load_matrix_sync(af, shQ + (wms * 16) * AST + k, AST);
#pragma unroll
                for (int j = 0; j < 2; j++) {
                    wmma::fragment<wmma::matrix_b, 16, 16, 8, wmma::precision::tf32, wmma::col_major> bf;
                    wmma::load_matrix_sync(bf, kb + (wns * 32 + j * 16) * AST + k, AST);
                    wmma::mma_sync(accs[j], af, bf, accs[j]);
                }
            }
#pragma unroll
            for (int j = 0; j < 2; j++)
                wmma::store_matrix_sync(
                    shS + (wms * 16) * SST + s * 64 + wns * 32 + j * 16,
                    accs[j], SST, wmma::mem_row_major);
        }
        __syncthreads();   // S complete

        // ---- per-block softmax over 256 keys (V0 load overlaps this) ----
        // Columns beyond send*64+63 on the diagonal are masked by the c>qoff
        // test (cbase >= 64*(pdiag+1) > qoff), so skipped subtiles get w=0.
        {
            float* srow = shS + row * SST + part * 64;
            const bool diag = (jb == bi);
            const int cbase = part * 64;

            float mx = -3.0e38f;
#pragma unroll 8
            for (int c = 0; c < 64; c++) {
                bool masked = diag && (cbase + c > qoff);
                float s = srow[c];
                if (!masked) mx = fmaxf(mx, s);
            }
            mx = fmaxf(mx, __shfl_xor_sync(0xffffffffu, mx, 1));
            mx = fmaxf(mx, __shfl_xor_sync(0xffffffffu, mx, 2));
            mx *= ATT_SCALE;

            float sumv = 0.0f;
#pragma unroll 8
            for (int c = 0; c < 64; c++) {
                bool masked = diag && (cbase + c > qoff);
                float p = masked ? 0.0f : __expf(srow[c] * ATT_SCALE - mx);
                srow[c] = p;
                sumv += p;
            }
            sumv += __shfl_xor_sync(0xffffffffu, sumv, 1);
            sumv += __shfl_xor_sync(0xffffffffu, sumv, 2);
            float inv = 1.0f / sumv;
#pragma unroll 8
            for (int c = 0; c < 64; c++) srow[c] = to_tf32(srow[c] * inv);
        }

        // ---- PV phase: subtiles 0..send (P is zero beyond) ----
        for (int v = 0; v <= send; v++) {
            CP_WAIT(0);
            __syncthreads();    // also orders softmax writes before PV reads
            if (v < send)        load64(shKV[(send + v) & 1], Vj + (size_t)(v + 1) * 64 * Hv);
            else if (jb < bi)    load64(shKV[0], Kj + (size_t)BSv * Hv);  // K(jb+1,0)
            CP_COMMIT();

            const float* vb = shKV[(send + 1 + v) & 1];
#pragma unroll
            for (int k = 0; k < 64; k += 8) {
                wmma::fragment<wmma::matrix_a, 16, 16, 8, wmma::precision::tf32, wmma::row_major> af[2];
#pragma unroll
                for (int i = 0; i < 2; i++)
                    wmma::load_matrix_sync(af[i], shS + (wmo * 32 + i * 16) * SST + v * 64 + k, SST);
#pragma unroll
                for (int j = 0; j < 2; j++) {
                    wmma::fragment<wmma::matrix_b, 16, 16, 8, wmma::precision::tf32, wmma::row_major> bf;
                    wmma::load_matrix_sync(bf, vb + k * AST + wno * 32 + j * 16, AST);
#pragma unroll
                    for (int i = 0; i < 2; i++)
                        wmma::mma_sync(acc_o[i][j], af[i], bf, acc_o[i][j]);
                }
            }
        }
    }

    // ---- epilogue ----
    const float invc = 1.0f / ((float)(bi + 1) + 1e-6f);
#pragma unroll
    for (int i = 0; i < 2; i++)
#pragma unroll
        for (int j = 0; j < 2; j++) {
#pragma unroll
            for (int t = 0; t < acc_o[i][j].num_elements; t++)
                acc_o[i][j].x[t] = to_tf32(acc_o[i][j].x[t] * invc);
            wmma::store_matrix_sync(
                g_o + ((size_t)(b * Sv + qbase + wmo * 32 + i * 16)) * Hv + h * HDv + wno * 32 + j * 16,
                acc_o[i][j], Hv, wmma::mem_row_major);
        }
}

// ===========================================================================
// launch
// ===========================================================================
extern "C" void kernel_launch(void* const* d_in, const int* in_sizes, int n_in,
                              void* d_out, int out_size)
{
    const float* X  = (const float*)d_in[0];
    const float* Wq = (const float*)d_in[1];
    const float* Wk = (const float*)d_in[2];
    const float* Wv = (const float*)d_in[3];
    const float* Wo = (const float*)d_in[4];
    float* out = (float*)d_out;

    float *q, *k, *v, *o, *xr, *wq, *wk, *wv, *wo;
    cudaGetSymbolAddress((void**)&q,  g_q);
    cudaGetSymbolAddress((void**)&k,  g_k);
    cudaGetSymbolAddress((void**)&v,  g_v);
    cudaGetSymbolAddress((void**)&o,  g_o);
    cudaGetSymbolAddress((void**)&xr, g_xr);
    cudaGetSymbolAddress((void**)&wq, g_wq);
    cudaGetSymbolAddress((void**)&wk, g_wk);
    cudaGetSymbolAddress((void**)&wv, g_wv);
    cudaGetSymbolAddress((void**)&wo, g_wo);

    const size_t attn_smem = (size_t)(3 * QT * AST + QT * SST) * sizeof(float);  // 167936

    cudaFuncSetAttribute(gemm_pipe, cudaFuncAttributeMaxDynamicSharedMemorySize, GEMM_SMEM);
    cudaFuncSetAttribute(attn_kernel, cudaFuncAttributeMaxDynamicSharedMemorySize, (int)attn_smem);

    // RNA-round all inputs to tf32 in one launch.
    round_all_k<<<(NX4 + 4 * NW4) / 256, 256>>>(
        (const float4*)X, (const float4*)Wq, (const float4*)Wk,
        (const float4*)Wv, (const float4*)Wo);

    dim3 gg(Hv / BN, Mtot / BM);     // (16, 16) = 256 CTAs
    gemm_pipe<<<gg, 256, GEMM_SMEM>>>(xr, wq, q, Mtot, Hv, Hv, 1);
    gemm_pipe<<<gg, 256, GEMM_SMEM>>>(xr, wk, k, Mtot, Hv, Hv, 1);
    gemm_pipe<<<gg, 256, GEMM_SMEM>>>(xr, wv, v, Mtot, Hv, Hv, 1);

    dim3 ag(Sv / QT, NHv, Bv);       // (32, 16, 2)
    attn_kernel<<<ag, 256, attn_smem>>>();

    gemm_pipe<<<gg, 256, GEMM_SMEM>>>(o, wo, out, Mtot, Hv, Hv, 0);
}

// round 8
// speedup vs baseline: 1.5900x; 1.5900x over previous
#include <cuda_runtime.h>
#include <mma.h>
#include <cstdint>
#include <cstddef>

using namespace nvcuda;

#define Bv   2
#define Sv   2048
#define Hv   2048
#define NHv  16
#define HDv  128
#define BSv  256
#define Mtot (Bv * Sv)
#define ATT_SCALE 0.08838834764831843f  // 1/sqrt(128)

// ---------------- scratch (__device__ globals, allocation-free rule) -------
__device__ float g_q[(size_t)Mtot * Hv];
__device__ float g_k[(size_t)Mtot * Hv];
__device__ float g_v[(size_t)Mtot * Hv];
__device__ float g_o[(size_t)Mtot * Hv];
__device__ float g_xr[(size_t)Mtot * Hv];
__device__ float g_wq[(size_t)Hv * Hv];
__device__ float g_wk[(size_t)Hv * Hv];
__device__ float g_wv[(size_t)Hv * Hv];
__device__ float g_wo[(size_t)Hv * Hv];

// ---------------- helpers ---------------------------------------------------
__device__ __forceinline__ float to_tf32(float x) {
    float y;
    asm("cvt.rna.tf32.f32 %0, %1;" : "=f"(y) : "f"(x));
    return y;
}

__device__ __forceinline__ uint32_t smem_u32(const void* p) {
    uint32_t a;
    asm("{ .reg .u64 t; cvta.to.shared.u64 t, %1; cvt.u32.u64 %0, t; }" : "=r"(a) : "l"(p));
    return a;
}

__device__ __forceinline__ void cp_async16(uint32_t saddr, const void* gptr) {
    asm volatile("cp.async.cg.shared.global [%0], [%1], 16;" :: "r"(saddr), "l"(gptr));
}
#define CP_COMMIT() asm volatile("cp.async.commit_group;")
#define CP_WAIT(n)  asm volatile("cp.async.wait_group %0;" :: "n"(n))

// ---------------- merged rounding pre-pass (one launch) ---------------------
#define NX4 (Mtot * Hv / 4)   // 2,097,152
#define NW4 (Hv * Hv / 4)     // 1,048,576

__global__ void __launch_bounds__(256) round_all_k(
    const float4* __restrict__ X,  const float4* __restrict__ Wq,
    const float4* __restrict__ Wk, const float4* __restrict__ Wv,
    const float4* __restrict__ Wo)
{
    int i = blockIdx.x * 256 + threadIdx.x;
    const float4* s; float4* d; int off;
    if (i < NX4)               { s = X;  d = (float4*)g_xr; off = i; }
    else if (i < NX4 + NW4)    { s = Wq; d = (float4*)g_wq; off = i - NX4; }
    else if (i < NX4 + 2*NW4)  { s = Wk; d = (float4*)g_wk; off = i - NX4 - NW4; }
    else if (i < NX4 + 3*NW4)  { s = Wv; d = (float4*)g_wv; off = i - NX4 - 2*NW4; }
    else                       { s = Wo; d = (float4*)g_wo; off = i - NX4 - 3*NW4; }
    float4 v = s[off];
    v.x = to_tf32(v.x); v.y = to_tf32(v.y);
    v.z = to_tf32(v.z); v.w = to_tf32(v.w);
    d[off] = v;
}

// ===========================================================================
// Pipelined tf32 wmma GEMM — EXACT R4 configuration (best measured):
// CTA tile 256x128x32, 8 warps (4x2) with 64x64 warp tiles, 4-stage cp.async,
// 1 CTA/SM. do_round=1 -> epilogue RNA-rounds C to tf32.
// ===========================================================================
#define BM 256
#define BN 128
#define BK 32
#define STR 36                       // 32 + 4 pad floats; 144B rows (16B-aligned)
#define NSTG 4
#define A_FLTS (BM * STR)            // 9216
#define B_FLTS (BN * STR)            // 4608
#define STAGE_FLTS (A_FLTS + B_FLTS) // 13824
#define GEMM_SMEM (NSTG * STAGE_FLTS * 4)   // 221184 B -> 1 CTA/SM

__device__ __forceinline__ void stage_load(
    float* stg, const float* __restrict__ Ag, const float* __restrict__ Bg,
    int K, int tid)
{
#pragma unroll
    for (int i = 0; i < 8; i++) {      // A: 256 rows x 8 x 16B
        int id = tid + i * 256;
        int r = id >> 3, c = id & 7;
        cp_async16(smem_u32(stg + r * STR + c * 4), Ag + (size_t)r * K + c * 4);
    }
#pragma unroll
    for (int i = 0; i < 4; i++) {      // B: 128 rows x 8 x 16B
        int id = tid + i * 256;
        int r = id >> 3, c = id & 7;
        cp_async16(smem_u32(stg + A_FLTS + r * STR + c * 4), Bg + (size_t)r * K + c * 4);
    }
}

__global__ void __launch_bounds__(256, 1) gemm_pipe(
    const float* __restrict__ A, const float* __restrict__ Bw,
    float* __restrict__ C, int M, int N, int K, int do_round)
{
    extern __shared__ __align__(16) float sm[];

    const int tid = threadIdx.x;
    const int wid = tid >> 5;
    const int m0 = blockIdx.y * BM;
    const int n0 = blockIdx.x * BN;
    const int wm = wid & 3;    // 4 warp rows x 64 m
    const int wn = wid >> 2;   // 2 warp cols x 64 n

    const float* Abase = A + (size_t)m0 * K;
    const float* Bbase = Bw + (size_t)n0 * K;
    const int KT = K / BK;

    wmma::fragment<wmma::accumulator, 16, 16, 8, float> acc[4][4];
#pragma unroll
    for (int i = 0; i < 4; i++)
#pragma unroll
        for (int j = 0; j < 4; j++) wmma::fill_fragment(acc[i][j], 0.0f);

    // prologue: stages 0..NSTG-2 <- k-tiles 0..NSTG-2
#pragma unroll
    for (int t = 0; t < NSTG - 1; t++) {
        stage_load(sm + t * STAGE_FLTS, Abase + t * BK, Bbase + t * BK, K, tid);
        CP_COMMIT();
    }

    for (int kt = 0; kt < KT; kt++) {
        CP_WAIT(NSTG - 2);          // k-tile kt resident
        __syncthreads();            // also fences reads of the stage refilled below

        int tn = kt + NSTG - 1;
        if (tn < KT)
            stage_load(sm + (tn % NSTG) * STAGE_FLTS, Abase + (size_t)tn * BK,
                       Bbase + (size_t)tn * BK, K, tid);
        CP_COMMIT();

        const float* sA = sm + (kt % NSTG) * STAGE_FLTS;
        const float* sB = sA + A_FLTS;

#pragma unroll
        for (int kk = 0; kk < 4; kk++) {
            wmma::fragment<wmma::matrix_a, 16, 16, 8, wmma::precision::tf32, wmma::row_major> af[4];
            wmma::fragment<wmma::matrix_b, 16, 16, 8, wmma::precision::tf32, wmma::col_major> bf[4];
#pragma unroll
            for (int i = 0; i < 4; i++)
                wmma::load_matrix_sync(af[i], sA + (wm * 64 + i * 16) * STR + kk * 8, STR);
#pragma unroll
            for (int j = 0; j < 4; j++)
                wmma::load_matrix_sync(bf[j], sB + (wn * 64 + j * 16) * STR + kk * 8, STR);
#pragma unroll
            for (int j = 0; j < 4; j++)
#pragma unroll
                for (int i = 0; i < 4; i++)
                    wmma::mma_sync(acc[i][j], af[i], bf[j], acc[i][j]);
        }
    }

#pragma unroll
    for (int i = 0; i < 4; i++)
#pragma unroll
        for (int j = 0; j < 4; j++) {
            if (do_round) {
#pragma unroll
                for (int t = 0; t < acc[i][j].num_elements; t++)
                    acc[i][j].x[t] = to_tf32(acc[i][j].x[t]);
            }
            wmma::store_matrix_sync(
                C + (size_t)(m0 + wm * 64 + i * 16) * N + n0 + wn * 64 + j * 16,
                acc[i][j], N, wmma::mem_row_major);
        }
}

// ===========================================================================
// Attention with per-block softmax + diagonal-subtile skip (proven in R7).
// K/V subtiles double-buffered via cp.async, one subtile ahead.
// ===========================================================================
#define QT  64
#define AST 132   // 128 + 4 pad
#define SST 260   // 256 + 4 pad

__global__ void __launch_bounds__(256) attn_kernel()
{
    extern __shared__ __align__(16) float sm[];
    float* shQ  = sm;                          // [64][AST]
    float* shKV[2] = { shQ + QT * AST, shQ + 2 * QT * AST };
    float* shS  = shQ + 3 * QT * AST;          // [64][SST]

    const int tid = threadIdx.x;
    const int wid = tid >> 5;
    const int qt = blockIdx.x;
    const int h  = blockIdx.y;
    const int b  = blockIdx.z;
    const int qbase = qt * QT;
    const int bi = qbase >> 8;
    const int pdiag = (qbase >> 6) & 3;        // last needed subtile on diagonal

    const float* Qp    = g_q + ((size_t)b * Sv + qbase) * Hv + h * HDv;
    const float* Kbase = g_k + ((size_t)b * Sv) * Hv + h * HDv;
    const float* Vbase = g_v + ((size_t)b * Sv) * Hv + h * HDv;

    auto load64 = [&](float* dst, const float* src) {
#pragma unroll
        for (int i = 0; i < 8; i++) {
            int id = tid + i * 256;
            int r = id >> 5, c4 = id & 31;
            cp_async16(smem_u32(dst + r * AST + c4 * 4), src + (size_t)r * Hv + c4 * 4);
        }
    };

    load64(shQ, Qp);
    load64(shKV[0], Kbase);   // K(jb=0, sub=0)
    CP_COMMIT();

    wmma::fragment<wmma::accumulator, 16, 16, 8, float> acc_o[2][2];
#pragma unroll
    for (int i = 0; i < 2; i++)
#pragma unroll
        for (int j = 0; j < 2; j++) wmma::fill_fragment(acc_o[i][j], 0.0f);

    const int wms = wid & 3,  wns = wid >> 2;   // S phase: 16 rows x 32 cols
    const int wmo = wid & 1,  wno = wid >> 1;   // O phase: 32 rows x 32 cols

    const int row  = tid >> 2;
    const int part = tid & 3;
    const int qoff = (qbase & 255) + row;

    for (int jb = 0; jb <= bi; jb++) {
        const float* Kj = Kbase + (size_t)jb * BSv * Hv;
        const float* Vj = Vbase + (size_t)jb * BSv * Hv;
        const int send = (jb == bi) ? pdiag : 3;   // last subtile needed

        // ---- S phase: subtiles 0..send of 64 keys ----
        for (int s = 0; s <= send; s++) {
            CP_WAIT(0);
            __syncthreads();
            if (s < send)  load64(shKV[(s + 1) & 1], Kj + (size_t)(s + 1) * 64 * Hv);
            else           load64(shKV[(send + 1) & 1], Vj);          // V(jb,0)
            CP_COMMIT();

            const float* kb = shKV[s & 1];
            wmma::fragment<wmma::accumulator, 16, 16, 8, float> accs[2];
            wmma::fill_fragment(accs[0], 0.0f);
            wmma::fill_fragment(accs[1], 0.0f);
#pragma unroll
            for (int k = 0; k < HDv; k += 8) {
                wmma::fragment<wmma::matrix_a, 16, 16, 8, wmma::precision::tf32, wmma::row_major> af;
                wmma::load_matrix_sync(af, shQ + (wms * 16) * AST + k, AST);
#pragma unroll
                for (int j = 0; j < 2; j++) {
                    wmma::fragment<wmma::matrix_b, 16, 16, 8, wmma::precision::tf32, wmma::col_major> bf;
                    wmma::load_matrix_sync(bf, kb + (wns * 32 + j * 16) * AST + k, AST);
                    wmma::mma_sync(accs[j], af, bf, accs[j]);
                }
            }
#pragma unroll
            for (int j = 0; j < 2; j++)
                wmma::store_matrix_sync(
                    shS + (wms * 16) * SST + s * 64 + wns * 32 + j * 16,
                    accs[j], SST, wmma::mem_row_major);
        }
        __syncthreads();   // S complete

        // ---- per-block softmax over 256 keys (V0 load overlaps this) ----
        // Diagonal columns beyond send*64+63 are masked by c>qoff, so the
        // skipped subtiles contribute exactly zero weight.
        {
            float* srow = shS + row * SST + part * 64;
            const bool diag = (jb == bi);
            const int cbase = part * 64;

            float mx = -3.0e38f;
#pragma unroll 8
            for (int c = 0; c < 64; c++) {
                bool masked = diag && (cbase + c > qoff);
                float s = srow[c];
                if (!masked) mx = fmaxf(mx, s);
            }
            mx = fmaxf(mx, __shfl_xor_sync(0xffffffffu, mx, 1));
            mx = fmaxf(mx, __shfl_xor_sync(0xffffffffu, mx, 2));
            mx *= ATT_SCALE;

            float sumv = 0.0f;
#pragma unroll 8
            for (int c = 0; c < 64; c++) {
                bool masked = diag && (cbase + c > qoff);
                float p = masked ? 0.0f : __expf(srow[c] * ATT_SCALE - mx);
                srow[c] = p;
                sumv += p;
            }
            sumv += __shfl_xor_sync(0xffffffffu, sumv, 1);
            sumv += __shfl_xor_sync(0xffffffffu, sumv, 2);
            float inv = 1.0f / sumv;
#pragma unroll 8
            for (int c = 0; c < 64; c++) srow[c] = to_tf32(srow[c] * inv);
        }

        // ---- PV phase: subtiles 0..send (P is zero beyond) ----
        for (int v = 0; v <= send; v++) {
            CP_WAIT(0);
            __syncthreads();    // also orders softmax writes before PV reads
            if (v < send)        load64(shKV[(send + v) & 1], Vj + (size_t)(v + 1) * 64 * Hv);
            else if (jb < bi)    load64(shKV[0], Kj + (size_t)BSv * Hv);  // K(jb+1,0)
            CP_COMMIT();

            const float* vb = shKV[(send + 1 + v) & 1];
#pragma unroll
            for (int k = 0; k < 64; k += 8) {
                wmma::fragment<wmma::matrix_a, 16, 16, 8, wmma::precision::tf32, wmma::row_major> af[2];
#pragma unroll
                for (int i = 0; i < 2; i++)
                    wmma::load_matrix_sync(af[i], shS + (wmo * 32 + i * 16) * SST + v * 64 + k, SST);
#pragma unroll
                for (int j = 0; j < 2; j++) {
                    wmma::fragment<wmma::matrix_b, 16, 16, 8, wmma::precision::tf32, wmma::row_major> bf;
                    wmma::load_matrix_sync(bf, vb + k * AST + wno * 32 + j * 16, AST);
#pragma unroll
                    for (int i = 0; i < 2; i++)
                        wmma::mma_sync(acc_o[i][j], af[i], bf, acc_o[i][j]);
                }
            }
        }
    }

    // ---- epilogue ----
    const float invc = 1.0f / ((float)(bi + 1) + 1e-6f);
#pragma unroll
    for (int i = 0; i < 2; i++)
#pragma unroll
        for (int j = 0; j < 2; j++) {
#pragma unroll
            for (int t = 0; t < acc_o[i][j].num_elements; t++)
                acc_o[i][j].x[t] = to_tf32(acc_o[i][j].x[t] * invc);
            wmma::store_matrix_sync(
                g_o + ((size_t)(b * Sv + qbase + wmo * 32 + i * 16)) * Hv + h * HDv + wno * 32 + j * 16,
                acc_o[i][j], Hv, wmma::mem_row_major);
        }
}

// ===========================================================================
// launch
// ===========================================================================
extern "C" void kernel_launch(void* const* d_in, const int* in_sizes, int n_in,
                              void* d_out, int out_size)
{
    const float* X  = (const float*)d_in[0];
    const float* Wq = (const float*)d_in[1];
    const float* Wk = (const float*)d_in[2];
    const float* Wv = (const float*)d_in[3];
    const float* Wo = (const float*)d_in[4];
    float* out = (float*)d_out;

    float *q, *k, *v, *o, *xr, *wq, *wk, *wv, *wo;
    cudaGetSymbolAddress((void**)&q,  g_q);
    cudaGetSymbolAddress((void**)&k,  g_k);
    cudaGetSymbolAddress((void**)&v,  g_v);
    cudaGetSymbolAddress((void**)&o,  g_o);
    cudaGetSymbolAddress((void**)&xr, g_xr);
    cudaGetSymbolAddress((void**)&wq, g_wq);
    cudaGetSymbolAddress((void**)&wk, g_wk);
    cudaGetSymbolAddress((void**)&wv, g_wv);
    cudaGetSymbolAddress((void**)&wo, g_wo);

    const size_t attn_smem = (size_t)(3 * QT * AST + QT * SST) * sizeof(float);  // 167936

    cudaFuncSetAttribute(gemm_pipe, cudaFuncAttributeMaxDynamicSharedMemorySize, GEMM_SMEM);
    cudaFuncSetAttribute(attn_kernel, cudaFuncAttributeMaxDynamicSharedMemorySize, (int)attn_smem);

    // RNA-round all inputs to tf32 in one launch.
    round_all_k<<<(NX4 + 4 * NW4) / 256, 256>>>(
        (const float4*)X, (const float4*)Wq, (const float4*)Wk,
        (const float4*)Wv, (const float4*)Wo);

    dim3 gg(Hv / BN, Mtot / BM);     // (16, 16) = 256 CTAs
    gemm_pipe<<<gg, 256, GEMM_SMEM>>>(xr, wq, q, Mtot, Hv, Hv, 1);
    gemm_pipe<<<gg, 256, GEMM_SMEM>>>(xr, wk, k, Mtot, Hv, Hv, 1);
    gemm_pipe<<<gg, 256, GEMM_SMEM>>>(xr, wv, v, Mtot, Hv, Hv, 1);

    dim3 ag(Sv / QT, NHv, Bv);       // (32, 16, 2)
    attn_kernel<<<ag, 256, attn_smem>>>();

    gemm_pipe<<<gg, 256, GEMM_SMEM>>>(o, wo, out, Mtot, Hv, Hv, 0);
}